// round 2
// baseline (speedup 1.0000x reference)
#include <cuda_runtime.h>
#include <math.h>

#define NIMG 4
#define CIN 512
#define HH 64
#define WW 64
#define HW 4096
#define NANCH 36864   /* 64*64*9 */
#define PRE 6000
#define POST 300
#define KTOT 4608     /* 512*9 */

/* output layout (float32, concatenated in reference return order) */
#define OFF_LOCS   0
#define OFF_SCORES 589824
#define OFF_ROIS   884736
#define OFF_RIDX   889536
#define OFF_ANCH   890736

__device__ float   g_mid[NIMG * CIN * HW];       /* relu(conv1) */
__device__ float4  g_boxes[NIMG * NANCH];        /* clipped decoded boxes */
__device__ unsigned g_keys[NIMG * NANCH];        /* order-preserving score keys */
__device__ int     g_cand[NIMG * PRE];           /* sorted top-6000 anchor idx */
__device__ int     g_nvalid[NIMG];               /* # candidates with score > NEG */

__device__ __forceinline__ unsigned fkey(float f) {
    unsigned b = __float_as_uint(f);
    return (b & 0x80000000u) ? ~b : (b | 0x80000000u);
}

/* ============================================================
 * 3x3 conv as implicit GEMM: out[co, p] = sum_k W[co,k] * im2col[k, p]
 * BM=128 (co), BN=128 (px), BK=8, 256 threads, 8x8 per thread.
 * ============================================================ */
__global__ __launch_bounds__(256, 2)
void conv3x3_kernel(const float* __restrict__ in, const float* __restrict__ Wc,
                    const float* __restrict__ bc)
{
    __shared__ float As[8][128];
    __shared__ float Bs[8][128];

    const int t   = threadIdx.x;
    const int n   = blockIdx.z;
    const int co0 = blockIdx.y * 128;
    const int p0  = blockIdx.x * 128;

    const int am = t >> 1;
    const int ak = (t & 1) * 4;
    const int bk = t >> 5;
    const int bn = (t & 31) * 4;
    const int tx = t & 15;
    const int ty = t >> 4;

    const float* inN  = in + (size_t)n * CIN * HW;
    const float* Arow = Wc + (size_t)(co0 + am) * KTOT + ak;

    float acc[8][8];
#pragma unroll
    for (int i = 0; i < 8; i++)
#pragma unroll
        for (int j = 0; j < 8; j++) acc[i][j] = 0.f;

    for (int k0 = 0; k0 < KTOT; k0 += 8) {
        /* A tile: 128 co x 8 k */
        float4 a4 = *(const float4*)(Arow + k0);
        As[ak + 0][am] = a4.x;
        As[ak + 1][am] = a4.y;
        As[ak + 2][am] = a4.z;
        As[ak + 3][am] = a4.w;

        /* B tile: 8 k x 128 px (im2col gather) */
        {
            int kk = k0 + bk;
            int ci = kk / 9;
            int r  = kk - ci * 9;
            int ky = r / 3;
            int kx = r - ky * 3;
            ky -= 1; kx -= 1;
            const float* src = inN + ci * HW;
#pragma unroll
            for (int i = 0; i < 4; i++) {
                int p = p0 + bn + i;
                int y = (p >> 6) + ky;
                int x = (p & 63) + kx;
                float v = 0.f;
                if ((unsigned)y < 64u && (unsigned)x < 64u) v = src[(y << 6) + x];
                Bs[bk][bn + i] = v;
            }
        }
        __syncthreads();

#pragma unroll
        for (int k = 0; k < 8; k++) {
            float a[8], b[8];
            *(float4*)(a)     = *(const float4*)&As[k][ty * 8];
            *(float4*)(a + 4) = *(const float4*)&As[k][ty * 8 + 4];
            *(float4*)(b)     = *(const float4*)&Bs[k][tx * 8];
            *(float4*)(b + 4) = *(const float4*)&Bs[k][tx * 8 + 4];
#pragma unroll
            for (int i = 0; i < 8; i++)
#pragma unroll
                for (int j = 0; j < 8; j++) acc[i][j] += a[i] * b[j];
        }
        __syncthreads();
    }

    /* epilogue: bias + relu -> g_mid[n][co][p] */
    float* outN = g_mid + (size_t)n * CIN * HW;
#pragma unroll
    for (int i = 0; i < 8; i++) {
        int co = co0 + ty * 8 + i;
        float bv = bc[co];
        float4 v0, v1;
        v0.x = fmaxf(acc[i][0] + bv, 0.f);
        v0.y = fmaxf(acc[i][1] + bv, 0.f);
        v0.z = fmaxf(acc[i][2] + bv, 0.f);
        v0.w = fmaxf(acc[i][3] + bv, 0.f);
        v1.x = fmaxf(acc[i][4] + bv, 0.f);
        v1.y = fmaxf(acc[i][5] + bv, 0.f);
        v1.z = fmaxf(acc[i][6] + bv, 0.f);
        v1.w = fmaxf(acc[i][7] + bv, 0.f);
        float* dst = outN + (size_t)co * HW + p0 + tx * 8;
        *(float4*)(dst)     = v0;
        *(float4*)(dst + 4) = v1;
    }
}

/* ============================================================
 * 1x1 convs (score 18ch + loc 36ch), writes rpn_locs / rpn_scores
 * directly in transposed output layout.
 * block: 256 threads = 64 ch-slots x 4 pixel-groups of 16 px; tile BN=64 px.
 * ============================================================ */
__global__ __launch_bounds__(256)
void conv1x1_kernel(const float* __restrict__ Ws, const float* __restrict__ bs,
                    const float* __restrict__ Wl, const float* __restrict__ bl,
                    float* __restrict__ out)
{
    __shared__ float sm[16][64];
    const int t  = threadIdx.x;
    const int n  = blockIdx.y;
    const int p0 = blockIdx.x * 64;
    const int co = t & 63;
    const int pg = t >> 6;
    const bool active = co < 54;

    const float* mid  = g_mid + (size_t)n * CIN * HW;
    const float* wrow = (co < 18) ? (Ws + co * CIN) : (Wl + (co - 18) * CIN);

    float acc[16];
#pragma unroll
    for (int i = 0; i < 16; i++) acc[i] = 0.f;

    for (int k0 = 0; k0 < CIN; k0 += 16) {
        int l  = t * 4;
        int kk = l >> 6;
        int pp = l & 63;
        *(float4*)&sm[kk][pp] = *(const float4*)(mid + (size_t)(k0 + kk) * HW + p0 + pp);
        __syncthreads();
        if (active) {
#pragma unroll
            for (int k = 0; k < 16; k++) {
                float wv = __ldg(wrow + k0 + k);
#pragma unroll
                for (int p = 0; p < 16; p++) acc[p] += wv * sm[k][pg * 16 + p];
            }
        }
        __syncthreads();
    }

    if (active) {
        float bv = (co < 18) ? bs[co] : bl[co - 18];
#pragma unroll
        for (int p = 0; p < 16; p++) {
            int px = p0 + pg * 16 + p;
            float v = acc[p] + bv;
            if (co < 18) {
                int a = co >> 1, c = co & 1;
                out[OFF_SCORES + (((size_t)n * NANCH + (size_t)px * 9 + a) * 2 + c)] = v;
            } else {
                int lidx = co - 18;
                int a = lidx >> 2, c = lidx & 3;
                out[OFF_LOCS + (((size_t)n * NANCH + (size_t)px * 9 + a) * 4 + c)] = v;
            }
        }
    }
}

/* ============================================================
 * decode: anchors, loc2bbox, clip, min-size filter, 2-way softmax fg
 * ============================================================ */
__global__ void decode_kernel(float* __restrict__ out,
                              const int* __restrict__ p_ih, const int* __restrict__ p_iw)
{
    int i = blockIdx.x * blockDim.x + threadIdx.x;
    if (i >= NIMG * NANCH) return;
    int n   = i / NANCH;
    int j   = i - n * NANCH;
    int pos = j / 9;
    int a   = j - pos * 9;
    int y   = pos >> 6;
    int x   = pos & 63;

    /* base anchor in float64 (matches numpy), cast to f32, then f32 shift add */
    int ri = a / 3, si = a - ri * 3;
    double rr  = (ri == 0) ? 0.5 : ((ri == 1) ? 1.0 : 2.0);
    double ssc = (si == 0) ? 8.0 : ((si == 1) ? 16.0 : 32.0);
    double hh = 16.0 * ssc * sqrt(rr);
    double wd = 16.0 * ssc * sqrt(1.0 / rr);
    float sy = (float)(y * 16);
    float sx = (float)(x * 16);
    float ay0 = (float)(8.0 - hh * 0.5) + sy;
    float ax0 = (float)(8.0 - wd * 0.5) + sx;
    float ay1 = (float)(8.0 + hh * 0.5) + sy;
    float ax1 = (float)(8.0 + wd * 0.5) + sx;

    if (n == 0) {
        out[OFF_ANCH + (size_t)j * 4 + 0] = ay0;
        out[OFF_ANCH + (size_t)j * 4 + 1] = ax0;
        out[OFF_ANCH + (size_t)j * 4 + 2] = ay1;
        out[OFF_ANCH + (size_t)j * 4 + 3] = ax1;
    }

    const float* lp = out + OFF_LOCS + ((size_t)n * NANCH + j) * 4;
    float dy = lp[0], dx = lp[1], dh = lp[2], dw = lp[3];

    float ah = ay1 - ay0, aw = ax1 - ax0;
    float cy = ay0 + 0.5f * ah, cx = ax0 + 0.5f * aw;
    float ncy = dy * ah + cy;
    float ncx = dx * aw + cx;
    float nh  = expf(dh) * ah;
    float nw  = expf(dw) * aw;

    int ihv = p_ih[0], iwv = p_iw[0];
    float fh = (ihv > 262144) ? __int_as_float(ihv) : (float)ihv;
    float fw = (iwv > 262144) ? __int_as_float(iwv) : (float)iwv;

    float y0 = fminf(fmaxf(ncy - 0.5f * nh, 0.f), fh);
    float x0 = fminf(fmaxf(ncx - 0.5f * nw, 0.f), fw);
    float y1 = fminf(fmaxf(ncy + 0.5f * nh, 0.f), fh);
    float x1 = fminf(fmaxf(ncx + 0.5f * nw, 0.f), fw);

    bool ok = ((y1 - y0) >= 16.0f) && ((x1 - x0) >= 16.0f);

    const float* sp = out + OFF_SCORES + ((size_t)n * NANCH + j) * 2;
    float s0 = sp[0], s1 = sp[1];
    float m  = fmaxf(s0, s1);
    float e0 = expf(s0 - m), e1 = expf(s1 - m);
    float fg = e1 / (e0 + e1);

    float sc = ok ? fg : -1e10f;
    g_boxes[i] = make_float4(y0, x0, y1, x1);
    g_keys[i]  = fkey(sc);
}

/* ============================================================
 * per-image: radix-select 6000th key, gather top-6000 (ties by lowest
 * index, matching lax.top_k), bitonic sort desc by (key, ~idx).
 * one block of 1024 threads per image; 64KB dynamic smem for sort list.
 * ============================================================ */
__global__ __launch_bounds__(1024)
void select_kernel()
{
    extern __shared__ unsigned long long list[]; /* 8192 entries */
    __shared__ int hist[256];
    __shared__ unsigned sh_prefix, sh_prefmask;
    __shared__ int sh_K, sh_cnt, sh_eqbase;
    __shared__ int s_warpEq[32];

    const int n   = blockIdx.x;
    const int tid = threadIdx.x;
    const unsigned* keys = g_keys + (size_t)n * NANCH;

    if (tid == 0) { sh_prefix = 0; sh_prefmask = 0; sh_K = PRE; sh_cnt = 0; sh_eqbase = 0; }
    __syncthreads();

    /* 4-pass radix select for the PRE-th largest key */
    for (int byte = 3; byte >= 0; byte--) {
        for (int b = tid; b < 256; b += 1024) hist[b] = 0;
        __syncthreads();
        unsigned pf = sh_prefix, pm = sh_prefmask;
        for (int i = tid; i < NANCH; i += 1024) {
            unsigned u = keys[i];
            if ((u & pm) == pf) atomicAdd(&hist[(u >> (byte * 8)) & 255], 1);
        }
        __syncthreads();
        if (tid == 0) {
            int K = sh_K, cum = 0, b = 255;
            for (; b > 0; b--) {
                if (cum + hist[b] >= K) break;
                cum += hist[b];
            }
            sh_prefix  |= ((unsigned)b) << (byte * 8);
            sh_prefmask |= 0xFFu << (byte * 8);
            sh_K = K - cum;
        }
        __syncthreads();
    }
    const unsigned T = sh_prefix;
    const int needEq = sh_K;

    /* gather: all > T plus first needEq == T (by ascending index) */
    const int wid = tid >> 5, lane = tid & 31;
    for (int base = 0; base < NANCH; base += 1024) {
        int i = base + tid;
        unsigned u = keys[i];
        bool above = (u > T);
        bool eq    = (u == T);
        unsigned mask = __ballot_sync(0xFFFFFFFFu, eq);
        if (lane == 0) s_warpEq[wid] = __popc(mask);
        if (above) {
            int p = atomicAdd(&sh_cnt, 1);
            list[p] = ((unsigned long long)u << 32) | (unsigned)(~(unsigned)i);
        }
        __syncthreads();
        if (eq) {
            int pre = 0;
            for (int w2 = 0; w2 < wid; w2++) pre += s_warpEq[w2];
            int rank = sh_eqbase + pre + __popc(mask & ((1u << lane) - 1u));
            if (rank < needEq) {
                int p = atomicAdd(&sh_cnt, 1);
                list[p] = ((unsigned long long)u << 32) | (unsigned)(~(unsigned)i);
            }
        }
        __syncthreads();
        if (tid == 0) {
            int tot = 0;
            for (int w2 = 0; w2 < 32; w2++) tot += s_warpEq[w2];
            sh_eqbase += tot;
        }
        __syncthreads();
    }

    for (int r = PRE + tid; r < 8192; r += 1024) list[r] = 0ull;
    __syncthreads();

    /* bitonic sort, descending */
    for (int k = 2; k <= 8192; k <<= 1)
        for (int j = k >> 1; j > 0; j >>= 1) {
            for (int i = tid; i < 8192; i += 1024) {
                int ixj = i ^ j;
                if (ixj > i) {
                    unsigned long long A = list[i], B = list[ixj];
                    if (((i & k) == 0) ? (A < B) : (A > B)) { list[i] = B; list[ixj] = A; }
                }
            }
            __syncthreads();
        }

    const unsigned negk = fkey(-1e10f);
    for (int r = tid; r < PRE; r += 1024) {
        unsigned long long v = list[r];
        unsigned key = (unsigned)(v >> 32);
        int idx = (int)(~(unsigned)v);
        g_cand[n * PRE + r] = idx;
        bool valid = key > negk;
        if (valid) {
            unsigned nk2 = (r < PRE - 1) ? (unsigned)(list[r + 1] >> 32) : 0u;
            if (r == PRE - 1 || nk2 <= negk) g_nvalid[n] = r + 1;
        } else if (r == 0) {
            g_nvalid[n] = 0;
        }
    }
}

/* ============================================================
 * greedy NMS over sorted candidates (== reference scan semantics),
 * one block per image.
 * ============================================================ */
__global__ __launch_bounds__(1024)
void nms_kernel(float* __restrict__ out)
{
    extern __shared__ unsigned char smraw[];
    float4* sbox = (float4*)smraw;                                /* 6000 * 16B */
    unsigned char* supp = (unsigned char*)(sbox + PRE);           /* 6000 B */
    int* keep = (int*)(smraw + PRE * 16 + 6400);                  /* 300 * 4B */
    __shared__ int s_cur, s_nk, s_pick, s_done;

    const int n   = blockIdx.x;
    const int tid = threadIdx.x;

    for (int r = tid; r < PRE; r += 1024) {
        int idx = g_cand[n * PRE + r];
        sbox[r] = g_boxes[(size_t)n * NANCH + idx];
        supp[r] = 0;
    }
    if (tid == 0) { s_cur = 0; s_nk = 0; }
    const int limit = g_nvalid[n];
    __syncthreads();

    while (true) {
        if (tid == 0) {
            int c = s_cur;
            while (c < limit && supp[c]) c++;
            if (c >= limit || s_nk >= POST) {
                s_done = 1;
            } else {
                s_done = 0;
                s_pick = c;
                keep[s_nk] = c;
                s_nk = s_nk + 1;
                s_cur = c + 1;
            }
        }
        __syncthreads();
        if (s_done) break;

        float4 bb = sbox[s_pick];
        float a1 = (bb.z - bb.x) * (bb.w - bb.y);
        for (int j = s_pick + 1 + tid; j < PRE; j += 1024) {
            if (supp[j]) continue;
            float4 cb = sbox[j];
            float ty = fmaxf(bb.x, cb.x);
            float tx = fmaxf(bb.y, cb.y);
            float by = fminf(bb.z, cb.z);
            float bx = fminf(bb.w, cb.w);
            float inter = fmaxf(by - ty, 0.f) * fmaxf(bx - tx, 0.f);
            float a2 = (cb.z - cb.x) * (cb.w - cb.y);
            float iou = inter / (a1 + a2 - inter + 1e-9f);
            if (iou > 0.7f) supp[j] = 1;
        }
        __syncthreads();
    }

    const int nk = s_nk;
    for (int k2 = tid; k2 < POST; k2 += 1024) {
        float4 b = make_float4(0.f, 0.f, 0.f, 0.f);
        if (k2 < nk) b = sbox[keep[k2]];
        size_t o = OFF_ROIS + ((size_t)n * POST + k2) * 4;
        out[o + 0] = b.x;
        out[o + 1] = b.y;
        out[o + 2] = b.z;
        out[o + 3] = b.w;
        out[OFF_RIDX + (size_t)n * POST + k2] = (float)n;
    }
}

extern "C" void kernel_launch(void* const* d_in, const int* in_sizes, int n_in,
                              void* d_out, int out_size)
{
    const float* base_feat = (const float*)d_in[0];
    const float* Wc  = (const float*)d_in[1];
    const float* bc  = (const float*)d_in[2];
    const float* Wsc = (const float*)d_in[3];
    const float* bsc = (const float*)d_in[4];
    const float* Wl  = (const float*)d_in[5];
    const float* bl  = (const float*)d_in[6];
    const int*   ih  = (const int*)d_in[7];
    const int*   iw  = (const int*)d_in[8];
    float* out = (float*)d_out;

    (void)in_sizes; (void)n_in; (void)out_size;

    cudaFuncSetAttribute(select_kernel, cudaFuncAttributeMaxDynamicSharedMemorySize, 65536);
    cudaFuncSetAttribute(nms_kernel, cudaFuncAttributeMaxDynamicSharedMemorySize, 110592);

    conv3x3_kernel<<<dim3(32, 4, NIMG), 256>>>(base_feat, Wc, bc);
    conv1x1_kernel<<<dim3(64, NIMG), 256>>>(Wsc, bsc, Wl, bl, out);
    decode_kernel<<<(NIMG * NANCH + 255) / 256, 256>>>(out, ih, iw);
    select_kernel<<<NIMG, 1024, 65536>>>();
    nms_kernel<<<NIMG, 1024, 110592>>>(out);
}